// round 10
// baseline (speedup 1.0000x reference)
#include <cuda_runtime.h>
#include <cuda_bf16.h>
#include <mma.h>
#include <cstdint>

using namespace nvcuda;

// ---------------------------------------------------------------------------
// CMAFM block, fully fused, tensor-core GEMMs via WMMA bf16 split-2.
// One CTA per 8x8 window, 4096 CTAs, 256 threads (8 warps).
// GEMM: D[64 px][128 outch] = X[64][CIN] . W^T, wmma m16n16k16 bf16->f32.
// Split-2: D = Xhi.Whi + Xhi.Wlo + Xlo.Whi  (~1e-5 rel err).
// Weights pre-split to bf16 hi/lo in global (preproc kernels), staged per
// 64-k half via cp.async, overlapped with the X fp32->bf16 conversion.
// Attention / gating / BN+SiLU: validated SIMT fp32 (f32x2) code.
// ---------------------------------------------------------------------------

#define TB 256
using u64 = unsigned long long;

constexpr int CC = 128, HH = 256, WWI = 256, NPIX = 64, XP = 132;
constexpr int BUF = NPIX * XP;                 // 8448 floats per data buffer
constexpr size_t NTOT = 4ull * 128 * 256 * 256;

constexpr int WP = 72;                         // bf16 pitch for W-stage/X-tiles
// smem byte layout
constexpr int WST_HI = 5 * BUF * 4;            // 168960: W-hi [128][72] bf16
constexpr int WST_LO = WST_HI + 128 * WP * 2;  // 187392
constexpr int XT_HI  = WST_LO + 128 * WP * 2;  // 205824: X-hi [64][72] bf16
constexpr int XT_LO  = XT_HI + 64 * WP * 2;    // 215040
constexpr int SMEM_BYTES = XT_LO + 64 * WP * 2;// 224256

// pre-split weights: per matrix, hi [128][CIN] bf16 then lo [128][CIN]
__device__ __align__(16) __nv_bfloat16 g_w2[458752];
enum { OW_QO = 0,      OW_KO = 32768,  OW_VO = 65536,  OW_QS = 98304,
       OW_KS = 131072, OW_VS = 163840, OW_PO = 196608, OW_PS = 229376,
       OW_GO = 262144, OW_GS = 327680, OW_FW = 393216 };

struct P {
    const float *F_opt, *F_sar;
    const float *bq_opt, *bk_opt, *bv_opt, *bq_sar, *bk_sar, *bv_sar;
    const float *pb_o2s, *pb_s2o, *gob, *gsb, *fb;
    const float *gma, *bta, *mu, *var;
    float *out;
};

// ---- helpers --------------------------------------------------------------
__device__ __forceinline__ void f2fma(u64& d, u64 a, u64 b) {
    asm("fma.rn.f32x2 %0, %1, %2, %0;" : "+l"(d) : "l"(a), "l"(b));
}
__device__ __forceinline__ u64 f2mul(u64 a, u64 b) {
    u64 d; asm("mul.rn.f32x2 %0, %1, %2;" : "=l"(d) : "l"(a), "l"(b)); return d;
}
__device__ __forceinline__ u64 f2add(u64 a, u64 b) {
    u64 d; asm("add.rn.f32x2 %0, %1, %2;" : "=l"(d) : "l"(a), "l"(b)); return d;
}
__device__ __forceinline__ u64 dup2(float v) {
    u64 d; asm("mov.b64 %0, {%1, %1};" : "=l"(d) : "f"(v)); return d;
}
__device__ __forceinline__ float f2sum(u64 a) {
    float lo, hi; asm("mov.b64 {%0, %1}, %2;" : "=f"(lo), "=f"(hi) : "l"(a));
    return lo + hi;
}
__device__ __forceinline__ void cp16(uint32_t s, const void* g) {
    asm volatile("cp.async.cg.shared.global [%0], [%1], 16;" :: "r"(s), "l"(g));
}
__device__ __forceinline__ float sigmoidf_(float x) {
    return 1.f / (1.f + __expf(-x));
}

// ---------------------------------------------------------------------------
// Preproc: split W (fp32, n elems) into bf16 hi/lo at g_w2[dstOff], row-major.
// ---------------------------------------------------------------------------
__global__ void preproc(const float* __restrict__ W, int n, int dstOff) {
    const int i = blockIdx.x * 256 + threadIdx.x;
    if (i < n) {
        float x = W[i];
        __nv_bfloat16 h = __float2bfloat16_rn(x);
        __nv_bfloat16 l = __float2bfloat16_rn(x - __bfloat162float(h));
        g_w2[dstOff + i] = h;
        g_w2[dstOff + n + i] = l;
    }
}

// ---------------------------------------------------------------------------
// Window load/store (NCHW <-> smem [px][ch], pitch XP)
// ---------------------------------------------------------------------------
__device__ __forceinline__ void load_window(float* dst, const float* __restrict__ src,
                                            int gbase, int tid) {
    const int c = tid >> 1, qq = tid & 1;
    const float* s = src + gbase + c * (HH * WWI) + qq * 4;
#pragma unroll
    for (int i = 0; i < 8; ++i) {
        float4 v = *(const float4*)(s + i * WWI);
        float* d = dst + (i * 8 + qq * 4) * XP + c;
        d[0] = v.x; d[XP] = v.y; d[2 * XP] = v.z; d[3 * XP] = v.w;
    }
}
__device__ __forceinline__ void store_window(float* __restrict__ g, const float* sbuf,
                                             int gbase, int tid) {
    const int c = tid >> 1, qq = tid & 1;
    float* gp = g + gbase + c * (HH * WWI) + qq * 4;
    const float* sp0 = sbuf + qq * 4 * XP + c;
#pragma unroll
    for (int i = 0; i < 8; ++i) {
        const float* sp = sp0 + i * 8 * XP;
        *(float4*)(gp + i * WWI) = make_float4(sp[0], sp[XP], sp[2 * XP], sp[3 * XP]);
    }
}

// ---------------------------------------------------------------------------
// WMMA GEMM: outb[px][ch] = [x0|x1][px][CIN] . W^T + bias.
// Per 64-k half: cp.async W hi/lo (pre-split, row-major) into stage while
// converting the X half to bf16 hi/lo tiles; then 4 k16 chunks of wmma.
// Warp w: row-tile (w&3)*16, col-tiles (w>>2)*64 + j*16 (j<4).
// In-place (outb == x0) safe: outb written only in epilogue.
// ---------------------------------------------------------------------------
__device__ __noinline__ void gemm_tc(int matOff, int CIN, const float* __restrict__ bias,
                                     const float* x0, const float* x1,
                                     float* outb, char* smem_c, uint32_t sbase) {
    const int tid = threadIdx.x;
    const int w = tid >> 5;
    const int nh = CIN >> 6;
    __nv_bfloat16* WH = (__nv_bfloat16*)(smem_c + WST_HI);
    __nv_bfloat16* WL = (__nv_bfloat16*)(smem_c + WST_LO);
    __nv_bfloat16* XH = (__nv_bfloat16*)(smem_c + XT_HI);
    __nv_bfloat16* XL = (__nv_bfloat16*)(smem_c + XT_LO);
    const int rowTile = (w & 3) * 16;
    const int colBase = (w >> 2) * 64;

    wmma::fragment<wmma::accumulator, 16, 16, 16, float> acc[4];
#pragma unroll
    for (int j = 0; j < 4; ++j) wmma::fill_fragment(acc[j], 0.0f);

    for (int h = 0; h < nh; ++h) {
        __syncthreads();  // prior readers of stage/tiles done
        // stage W half h (hi+lo) via cp.async
        {
            const __nv_bfloat16* GH = g_w2 + matOff + h * 64;
            const __nv_bfloat16* GL = GH + 128 * CIN;
#pragma unroll
            for (int it = 0; it < 4; ++it) {
                const int s = tid + it * 256;      // 0..1023
                const int r = s >> 3, sg = s & 7;  // row, 16B segment
                cp16(sbase + WST_HI + r * (WP * 2) + sg * 16, GH + r * CIN + sg * 8);
                cp16(sbase + WST_LO + r * (WP * 2) + sg * 16, GL + r * CIN + sg * 8);
            }
            asm volatile("cp.async.commit_group;");
        }
        // convert X half -> bf16 hi/lo tiles (overlaps the cp.async flight)
        {
            const float* xs = (h >= 2 ? x1 + (h - 2) * 64 : x0 + h * 64);
            const int r = tid >> 2;           // 0..63
            const int c0 = (tid & 3) * 16;    // 0..48
            const float* xr = xs + r * XP + c0;
            __nv_bfloat16* dh = XH + r * WP + c0;
            __nv_bfloat16* dl = XL + r * WP + c0;
#pragma unroll
            for (int q4 = 0; q4 < 4; ++q4) {
                float4 v = *(const float4*)(xr + q4 * 4);
                __nv_bfloat162 h0, h1, l0, l1;
                h0.x = __float2bfloat16_rn(v.x); h0.y = __float2bfloat16_rn(v.y);
                h1.x = __float2bfloat16_rn(v.z); h1.y = __float2bfloat16_rn(v.w);
                l0.x = __float2bfloat16_rn(v.x - __bfloat162float(h0.x));
                l0.y = __float2bfloat16_rn(v.y - __bfloat162float(h0.y));
                l1.x = __float2bfloat16_rn(v.z - __bfloat162float(h1.x));
                l1.y = __float2bfloat16_rn(v.w - __bfloat162float(h1.y));
                *(__nv_bfloat162*)(dh + q4 * 4)     = h0;
                *(__nv_bfloat162*)(dh + q4 * 4 + 2) = h1;
                *(__nv_bfloat162*)(dl + q4 * 4)     = l0;
                *(__nv_bfloat162*)(dl + q4 * 4 + 2) = l1;
            }
        }
        asm volatile("cp.async.wait_group 0;");
        __syncthreads();  // stage + tiles visible

#pragma unroll
        for (int kk = 0; kk < 4; ++kk) {
            wmma::fragment<wmma::matrix_a, 16, 16, 16, __nv_bfloat16, wmma::row_major> ah, al;
            wmma::load_matrix_sync(ah, XH + rowTile * WP + kk * 16, WP);
            wmma::load_matrix_sync(al, XL + rowTile * WP + kk * 16, WP);
#pragma unroll
            for (int j = 0; j < 4; ++j) {
                wmma::fragment<wmma::matrix_b, 16, 16, 16, __nv_bfloat16, wmma::col_major> bh, bl;
                const int cn = colBase + j * 16;
                wmma::load_matrix_sync(bh, WH + cn * WP + kk * 16, WP);
                wmma::load_matrix_sync(bl, WL + cn * WP + kk * 16, WP);
                wmma::mma_sync(acc[j], ah, bh, acc[j]);
                wmma::mma_sync(acc[j], ah, bl, acc[j]);
                wmma::mma_sync(acc[j], al, bh, acc[j]);
            }
        }
    }
    __syncthreads();  // all reads (incl. in-place x0) done before writes
#pragma unroll
    for (int j = 0; j < 4; ++j)
        wmma::store_matrix_sync(outb + rowTile * XP + colBase + j * 16, acc[j],
                                XP, wmma::mem_row_major);
    __syncthreads();
    for (int idx = tid; idx < NPIX * CC; idx += TB) {
        const int px = idx >> 7, ch = idx & 127;
        outb[px * XP + ch] += __ldg(bias + ch);
    }
    __syncthreads();
}

// ---------------------------------------------------------------------------
// Window attention (SIMT fp32, validated): 8 warps = 4 heads x 2 halves;
// lane owns one query row; single-pass no-max softmax. Ob may alias Qb.
// ---------------------------------------------------------------------------
__device__ __forceinline__ void attention(const float* __restrict__ Qb,
                                          const float* __restrict__ Kb,
                                          const float* __restrict__ Vb,
                                          float* __restrict__ Ob, int tid) {
    const int L = tid & 31, w = tid >> 5;
    const int head = w >> 1;
    const int row  = (w & 1) * 32 + L;

    u64 q[16];
    {
        const ulonglong2* qp = (const ulonglong2*)(Qb + row * XP + head * 32);
        const u64 sc2 = dup2(0.17677669529663687f);  // 32^-0.5
#pragma unroll
        for (int t = 0; t < 8; ++t) {
            ulonglong2 v = qp[t];
            q[2 * t]     = f2mul(v.x, sc2);
            q[2 * t + 1] = f2mul(v.y, sc2);
        }
    }
    __syncthreads();

    const float* kbase = Kb + head * 32;
    const float* vbase = Vb + head * 32;

    float l = 0.f;
    u64 o[16];
#pragma unroll
    for (int t = 0; t < 16; ++t) o[t] = 0ull;

    for (int j = 0; j < 64; ++j) {
        const ulonglong2* kp = (const ulonglong2*)(kbase + j * XP);
        u64 d0 = 0ull, d1 = 0ull, d2 = 0ull, d3 = 0ull;
#pragma unroll
        for (int t = 0; t < 4; ++t) {
            ulonglong2 ka = kp[2 * t], kb = kp[2 * t + 1];
            f2fma(d0, q[4 * t],     ka.x);
            f2fma(d1, q[4 * t + 1], ka.y);
            f2fma(d2, q[4 * t + 2], kb.x);
            f2fma(d3, q[4 * t + 3], kb.y);
        }
        const float e = __expf(f2sum(f2add(f2add(d0, d1), f2add(d2, d3))));
        l += e;
        const u64 ee = dup2(e);
        const ulonglong2* vp = (const ulonglong2*)(vbase + j * XP);
#pragma unroll
        for (int t = 0; t < 8; ++t) {
            ulonglong2 v2 = vp[t];
            f2fma(o[2 * t],     ee, v2.x);
            f2fma(o[2 * t + 1], ee, v2.y);
        }
    }
    const u64 inv2 = dup2(1.f / l);
    ulonglong2* op = (ulonglong2*)(Ob + row * XP + head * 32);
#pragma unroll
    for (int t = 0; t < 8; ++t) {
        ulonglong2 r;
        r.x = f2mul(o[2 * t], inv2);
        r.y = f2mul(o[2 * t + 1], inv2);
        op[t] = r;
    }
    __syncthreads();
}

extern __shared__ char smem_raw[];

__global__ void __launch_bounds__(TB, 1) cmafm_kernel(P p) {
    char* smem_c = smem_raw;
    float* smem = (float*)smem_raw;
    float* B0 = smem;
    float* B1 = smem + BUF;
    float* B2 = smem + 2 * BUF;
    float* B3 = smem + 3 * BUF;
    float* B4 = smem + 4 * BUF;

    uint32_t sbase;
    asm("{ .reg .u64 t; cvta.to.shared.u64 t, %1; cvt.u32.u64 %0, t; }"
        : "=r"(sbase) : "l"(smem_raw));

    const int tid  = threadIdx.x;
    const int widx = blockIdx.x;
    const int b  = widx >> 10;
    const int wh = (widx >> 5) & 31;
    const int ww = widx & 31;
    const int gbase = b * (CC * HH * WWI) + (wh * 8) * WWI + ww * 8;

    load_window(B0, p.F_opt, gbase, tid);
    load_window(B1, p.F_sar, gbase, tid);

    // --- direction opt->sar ---
    gemm_tc(OW_QO, 128, p.bq_opt, B0, nullptr, B2, smem_c, sbase);   // Qo
    gemm_tc(OW_KS, 128, p.bk_sar, B1, nullptr, B3, smem_c, sbase);   // Ks
    gemm_tc(OW_VS, 128, p.bv_sar, B1, nullptr, B4, smem_c, sbase);   // Vs
    attention(B2, B3, B4, B2, tid);
    gemm_tc(OW_PO, 128, p.pb_o2s, B2, nullptr, B3, smem_c, sbase);   // F_o2s -> B3

    // --- direction sar->opt ---
    gemm_tc(OW_QS, 128, p.bq_sar, B1, nullptr, B2, smem_c, sbase);   // Qs
    gemm_tc(OW_KO, 128, p.bk_opt, B0, nullptr, B4, smem_c, sbase);   // Ko
    gemm_tc(OW_VO, 128, p.bv_opt, B0, nullptr, B0, smem_c, sbase);   // Vo in-place
    attention(B2, B4, B0, B2, tid);
    load_window(B0, p.F_opt, gbase, tid);                            // reload F_opt
    gemm_tc(OW_PS, 128, p.pb_s2o, B2, nullptr, B4, smem_c, sbase);   // F_s2o -> B4

    // --- gate opt: sigma = sigmoid(Wg @ [F_opt ; F_o2s]) ---
    gemm_tc(OW_GO, 256, p.gob, B0, B3, B2, smem_c, sbase);
    for (int idx = tid; idx < NPIX * CC; idx += TB) {
        const int off = (idx >> 7) * XP + (idx & 127);
        const float s = sigmoidf_(B2[off]);
        B2[off] = s;
        B3[off] = B0[off] + s * B3[off];      // F_opt_new
    }
    __syncthreads();
    store_window(p.out + NTOT, B2, gbase, tid);      // sigma_opt

    // --- gate sar ---
    gemm_tc(OW_GS, 256, p.gsb, B1, B4, B0, smem_c, sbase);
    for (int idx = tid; idx < NPIX * CC; idx += TB) {
        const int off = (idx >> 7) * XP + (idx & 127);
        const float s = sigmoidf_(B0[off]);
        B0[off] = s;
        B4[off] = B1[off] + s * B4[off];      // F_sar_new
    }
    __syncthreads();
    store_window(p.out + 2 * NTOT, B0, gbase, tid);  // sigma_sar

    // --- fuse + BN + SiLU ---
    gemm_tc(OW_FW, 256, p.fb, B3, B4, B2, smem_c, sbase);
    {
        const int c = tid >> 1, qq = tid & 1;
        const float inv = p.gma[c] * rsqrtf(p.var[c] + 1e-5f);
        const float sh  = p.bta[c] - p.mu[c] * inv;
        float* g = p.out + gbase + c * (HH * WWI) + qq * 4;
        const float* sp0 = B2 + qq * 4 * XP + c;
#pragma unroll
        for (int i = 0; i < 8; ++i) {
            const float* sp = sp0 + i * 8 * XP;
            float y0 = sp[0]      * inv + sh;
            float y1 = sp[XP]     * inv + sh;
            float y2 = sp[2 * XP] * inv + sh;
            float y3 = sp[3 * XP] * inv + sh;
            y0 *= sigmoidf_(y0); y1 *= sigmoidf_(y1);
            y2 *= sigmoidf_(y2); y3 *= sigmoidf_(y3);
            *(float4*)(g + i * WWI) = make_float4(y0, y1, y2, y3);
        }
    }
}

// ---------------------------------------------------------------------------
extern "C" void kernel_launch(void* const* d_in, const int* in_sizes, int n_in,
                              void* d_out, int out_size) {
    (void)in_sizes; (void)n_in; (void)out_size;

    preproc<<<64,  256>>>((const float*)d_in[2],  16384, OW_QO);
    preproc<<<64,  256>>>((const float*)d_in[4],  16384, OW_KO);
    preproc<<<64,  256>>>((const float*)d_in[6],  16384, OW_VO);
    preproc<<<64,  256>>>((const float*)d_in[8],  16384, OW_QS);
    preproc<<<64,  256>>>((const float*)d_in[10], 16384, OW_KS);
    preproc<<<64,  256>>>((const float*)d_in[12], 16384, OW_VS);
    preproc<<<64,  256>>>((const float*)d_in[14], 16384, OW_PO);
    preproc<<<64,  256>>>((const float*)d_in[16], 16384, OW_PS);
    preproc<<<128, 256>>>((const float*)d_in[18], 32768, OW_GO);
    preproc<<<128, 256>>>((const float*)d_in[20], 32768, OW_GS);
    preproc<<<128, 256>>>((const float*)d_in[22], 32768, OW_FW);

    P p;
    p.F_opt  = (const float*)d_in[0];  p.F_sar  = (const float*)d_in[1];
    p.bq_opt = (const float*)d_in[3];  p.bk_opt = (const float*)d_in[5];
    p.bv_opt = (const float*)d_in[7];  p.bq_sar = (const float*)d_in[9];
    p.bk_sar = (const float*)d_in[11]; p.bv_sar = (const float*)d_in[13];
    p.pb_o2s = (const float*)d_in[15]; p.pb_s2o = (const float*)d_in[17];
    p.gob    = (const float*)d_in[19]; p.gsb    = (const float*)d_in[21];
    p.fb     = (const float*)d_in[23];
    p.gma    = (const float*)d_in[24]; p.bta    = (const float*)d_in[25];
    p.mu     = (const float*)d_in[26]; p.var    = (const float*)d_in[27];
    p.out    = (float*)d_out;

    cudaFuncSetAttribute(cmafm_kernel, cudaFuncAttributeMaxDynamicSharedMemorySize,
                         SMEM_BYTES);
    cmafm_kernel<<<4096, TB, SMEM_BYTES>>>(p);
}

// round 11
// speedup vs baseline: 1.1015x; 1.1015x over previous
#include <cuda_runtime.h>
#include <cuda_bf16.h>
#include <mma.h>
#include <cstdint>

using namespace nvcuda;

// ---------------------------------------------------------------------------
// CMAFM block as a pipeline of batched tensor-core GEMM kernels (WMMA bf16
// split-2, 3 terms: Whi.Xhi + Whi.Xlo + Wlo.Xhi, fp32 accum ~ 5e-6 rel) plus
// a window-attention kernel (validated SIMT fp32). Intermediates live in a
// __device__ scratch (DRAM is ~free here).
// GEMM kernel: D[128 ch_out][px] = W[128][CIN] . X[CIN][px]; CTA = 1024 px,
// W staged ONCE per CTA (amortized), 8 subtiles of 128 px; per subtile:
// convert X to bf16 hi/lo smem tiles, wmma mainloop, fused epilogue.
// ---------------------------------------------------------------------------

#define TB 256
using u64 = unsigned long long;

constexpr int CC = 128, HH = 256, WWI = 256, NPIX = 64, XP = 132;
constexpr int BUF = NPIX * XP;
constexpr size_t NTOT = 4ull * 128 * 256 * 256;       // 33,554,432
constexpr int IMG = 65536;                             // H*W
constexpr int CSTRIDE = IMG;                           // channel stride
constexpr int BSTRIDE = 128 * IMG;                     // batch stride

// scratch: 6 fp32 tensors of 33.5M
__device__ __align__(16) float g_scr[6ull * 33554432];

// pre-split weights: per matrix, hi [128][CIN] bf16 then lo [128][CIN]
__device__ __align__(16) __nv_bfloat16 g_w2[458752];
enum { OW_QO = 0,      OW_KO = 32768,  OW_VO = 65536,  OW_QS = 98304,
       OW_KS = 131072, OW_VS = 163840, OW_PO = 196608, OW_PS = 229376,
       OW_GO = 262144, OW_GS = 327680, OW_FW = 393216 };

enum { EPI_BIAS = 0, EPI_GATE = 1, EPI_FUSE = 2 };

struct GP {
    const float *x0, *x1;      // X inputs (x1 = second 128-ch half for CIN=256)
    int wOff;                  // offset into g_w2
    const float *bias;
    float *dst;                // main output tensor [B][128][H][W]
    float *sgm;                // GATE: sigma output
    const float *gma, *bta, *mu, *var;  // FUSE: BN params
};

// ---- helpers --------------------------------------------------------------
__device__ __forceinline__ void f2fma(u64& d, u64 a, u64 b) {
    asm("fma.rn.f32x2 %0, %1, %2, %0;" : "+l"(d) : "l"(a), "l"(b));
}
__device__ __forceinline__ u64 f2mul(u64 a, u64 b) {
    u64 d; asm("mul.rn.f32x2 %0, %1, %2;" : "=l"(d) : "l"(a), "l"(b)); return d;
}
__device__ __forceinline__ u64 f2add(u64 a, u64 b) {
    u64 d; asm("add.rn.f32x2 %0, %1, %2;" : "=l"(d) : "l"(a), "l"(b)); return d;
}
__device__ __forceinline__ u64 dup2(float v) {
    u64 d; asm("mov.b64 %0, {%1, %1};" : "=l"(d) : "f"(v)); return d;
}
__device__ __forceinline__ float f2sum(u64 a) {
    float lo, hi; asm("mov.b64 {%0, %1}, %2;" : "=f"(lo), "=f"(hi) : "l"(a));
    return lo + hi;
}
__device__ __forceinline__ void cp16(uint32_t s, const void* g) {
    asm volatile("cp.async.cg.shared.global [%0], [%1], 16;" :: "r"(s), "l"(g));
}
__device__ __forceinline__ float sigmoidf_(float x) {
    return 1.f / (1.f + __expf(-x));
}

// ---------------------------------------------------------------------------
// Preproc: split W (fp32, n elems) into bf16 hi/lo at g_w2[dstOff], row-major.
// ---------------------------------------------------------------------------
__global__ void preproc(const float* __restrict__ W, int n, int dstOff) {
    const int i = blockIdx.x * 256 + threadIdx.x;
    if (i < n) {
        float x = W[i];
        __nv_bfloat16 h = __float2bfloat16_rn(x);
        __nv_bfloat16 l = __float2bfloat16_rn(x - __bfloat162float(h));
        g_w2[dstOff + i] = h;
        g_w2[dstOff + n + i] = l;
    }
}

// ---------------------------------------------------------------------------
// Batched GEMM kernel. grid.x = 256 CTAs (1024 px each), 256 threads.
// ---------------------------------------------------------------------------
extern __shared__ char smem_g[];

template <int CIN, int EPI>
__global__ void __launch_bounds__(TB, 1) gemm_k(GP p) {
    constexpr int KP = CIN + 8;               // W pitch (bf16 elems)
    constexpr int NP = 136;                   // X tile pitch (bf16 elems)
    constexpr int DP = 132;                   // D smem pitch (fp32)
    constexpr int OFF_WL = 128 * KP;          // elems
    constexpr int OFF_X  = 2 * 128 * KP * 2;  // bytes

    const int tid = threadIdx.x;
    const int w = tid >> 5;
    const int px0 = blockIdx.x << 10;
    const int b = px0 >> 16;
    const int hw0 = px0 & (IMG - 1);

    uint32_t sbase;
    asm("{ .reg .u64 t; cvta.to.shared.u64 t, %1; cvt.u32.u64 %0, t; }"
        : "=r"(sbase) : "l"(smem_g));
    __nv_bfloat16* WH = (__nv_bfloat16*)smem_g;
    __nv_bfloat16* WL = WH + OFF_WL;
    __nv_bfloat16* XH = (__nv_bfloat16*)(smem_g + OFF_X);
    __nv_bfloat16* XL = XH + 128 * NP;
    float* Dsm = (float*)(smem_g + OFF_X);

    // --- stage full W (hi + lo) once, via cp.async ---
    {
        const __nv_bfloat16* gwh = g_w2 + p.wOff;
        const __nv_bfloat16* gwl = gwh + 128 * CIN;
        constexpr int SEG = CIN / 8;          // 16B segments per row
#pragma unroll
        for (int it = 0; it < CIN / 16; ++it) {
            const int s = tid + it * TB;      // 0 .. 128*SEG-1
            const int r = s / SEG, sg = s % SEG;
            cp16(sbase + (r * KP + sg * 8) * 2, gwh + r * CIN + sg * 8);
            cp16(sbase + (OFF_WL + r * KP + sg * 8) * 2, gwl + r * CIN + sg * 8);
        }
        asm volatile("cp.async.commit_group;");
    }

    // per-thread epilogue constants (thread owns channel c, px-half q)
    const int c = tid >> 1, q = tid & 1;
    const float bias_c = __ldg(p.bias + c);
    float inv_c = 0.f, sh_c = 0.f;
    if (EPI == EPI_FUSE) {
        inv_c = __ldg(p.gma + c) * rsqrtf(__ldg(p.var + c) + 1e-5f);
        sh_c  = __ldg(p.bta + c) - __ldg(p.mu + c) * inv_c;
    }

    wmma::fragment<wmma::accumulator, 16, 16, 16, float> acc[8];
#pragma unroll
    for (int nt = 0; nt < 8; ++nt) wmma::fill_fragment(acc[nt], 0.0f);

    for (int sub = 0; sub < 8; ++sub) {
        const int hw = hw0 + sub * 128;
#pragma unroll
        for (int kh = 0; kh < CIN / 128; ++kh) {
            // convert X chunk [128 ch][128 px] -> bf16 hi/lo tiles
            const float* Xsrc = (kh ? p.x1 : p.x0);
            const float* src = Xsrc + (size_t)b * BSTRIDE + c * CSTRIDE + hw + q * 64;
            __nv_bfloat16* dh = XH + c * NP + q * 64;
            __nv_bfloat16* dl = XL + c * NP + q * 64;
#pragma unroll
            for (int j = 0; j < 16; ++j) {
                float4 v = *(const float4*)(src + j * 4);
                __nv_bfloat162 h0, h1, l0, l1;
                h0.x = __float2bfloat16_rn(v.x); h0.y = __float2bfloat16_rn(v.y);
                h1.x = __float2bfloat16_rn(v.z); h1.y = __float2bfloat16_rn(v.w);
                l0.x = __float2bfloat16_rn(v.x - __bfloat162float(h0.x));
                l0.y = __float2bfloat16_rn(v.y - __bfloat162float(h0.y));
                l1.x = __float2bfloat16_rn(v.z - __bfloat162float(h1.x));
                l1.y = __float2bfloat16_rn(v.w - __bfloat162float(h1.y));
                *(__nv_bfloat162*)(dh + j * 4)     = h0;
                *(__nv_bfloat162*)(dh + j * 4 + 2) = h1;
                *(__nv_bfloat162*)(dl + j * 4)     = l0;
                *(__nv_bfloat162*)(dl + j * 4 + 2) = l1;
            }
            asm volatile("cp.async.wait_group 0;");  // W staged (first pass)
            __syncthreads();

            // wmma mainloop: warp w owns M-tile w, all 8 N-tiles
            const __nv_bfloat16* Ah = WH + w * 16 * KP + kh * 128;
            const __nv_bfloat16* Al = WL + w * 16 * KP + kh * 128;
#pragma unroll
            for (int kk = 0; kk < 8; ++kk) {
                wmma::fragment<wmma::matrix_a, 16, 16, 16, __nv_bfloat16,
                               wmma::row_major> ah, al;
                wmma::load_matrix_sync(ah, Ah + kk * 16, KP);
                wmma::load_matrix_sync(al, Al + kk * 16, KP);
#pragma unroll
                for (int nt = 0; nt < 8; ++nt) {
                    wmma::fragment<wmma::matrix_b, 16, 16, 16, __nv_bfloat16,
                                   wmma::row_major> bh, bl;
                    wmma::load_matrix_sync(bh, XH + kk * 16 * NP + nt * 16, NP);
                    wmma::load_matrix_sync(bl, XL + kk * 16 * NP + nt * 16, NP);
                    wmma::mma_sync(acc[nt], ah, bh, acc[nt]);
                    wmma::mma_sync(acc[nt], ah, bl, acc[nt]);
                    wmma::mma_sync(acc[nt], al, bh, acc[nt]);
                }
            }
            __syncthreads();  // all B reads done before D overlays XT
        }

        // epilogue: frags -> smem D -> fused scalar epilogue -> global
#pragma unroll
        for (int nt = 0; nt < 8; ++nt) {
            wmma::store_matrix_sync(Dsm + w * 16 * DP + nt * 16, acc[nt], DP,
                                    wmma::mem_row_major);
            wmma::fill_fragment(acc[nt], 0.0f);
        }
        __syncthreads();
        {
            const size_t ga = (size_t)b * BSTRIDE + c * CSTRIDE + hw + q * 64;
            const float* dp = Dsm + c * DP + q * 64;
#pragma unroll
            for (int j = 0; j < 16; ++j) {
                float4 v = *(const float4*)(dp + j * 4);
                v.x += bias_c; v.y += bias_c; v.z += bias_c; v.w += bias_c;
                if (EPI == EPI_BIAS) {
                    *(float4*)(p.dst + ga + j * 4) = v;
                } else if (EPI == EPI_GATE) {
                    float4 f  = *(const float4*)(p.x0 + ga + j * 4);
                    float4 fc = *(const float4*)(p.x1 + ga + j * 4);
                    float4 s;
                    s.x = sigmoidf_(v.x); s.y = sigmoidf_(v.y);
                    s.z = sigmoidf_(v.z); s.w = sigmoidf_(v.w);
                    *(float4*)(p.sgm + ga + j * 4) = s;
                    float4 r;
                    r.x = f.x + s.x * fc.x; r.y = f.y + s.y * fc.y;
                    r.z = f.z + s.z * fc.z; r.w = f.w + s.w * fc.w;
                    *(float4*)(p.dst + ga + j * 4) = r;
                } else {  // FUSE: BN + SiLU
                    float4 r;
                    r.x = v.x * inv_c + sh_c; r.y = v.y * inv_c + sh_c;
                    r.z = v.z * inv_c + sh_c; r.w = v.w * inv_c + sh_c;
                    r.x *= sigmoidf_(r.x); r.y *= sigmoidf_(r.y);
                    r.z *= sigmoidf_(r.z); r.w *= sigmoidf_(r.w);
                    *(float4*)(p.dst + ga + j * 4) = r;
                }
            }
        }
        __syncthreads();  // D consumed before next subtile conversion
    }
}

// ---------------------------------------------------------------------------
// Window attention kernel (SIMT fp32, validated): one CTA per 8x8 window.
// Reads Q,K,V (NCHW fp32) from scratch, writes O (NCHW) — O may alias Q.
// ---------------------------------------------------------------------------
__device__ __forceinline__ void load_window(float* dst, const float* __restrict__ src,
                                            int gbase, int tid) {
    const int c = tid >> 1, qq = tid & 1;
    const float* s = src + gbase + c * (HH * WWI) + qq * 4;
#pragma unroll
    for (int i = 0; i < 8; ++i) {
        float4 v = *(const float4*)(s + i * WWI);
        float* d = dst + (i * 8 + qq * 4) * XP + c;
        d[0] = v.x; d[XP] = v.y; d[2 * XP] = v.z; d[3 * XP] = v.w;
    }
}
__device__ __forceinline__ void store_window(float* __restrict__ g, const float* sbuf,
                                             int gbase, int tid) {
    const int c = tid >> 1, qq = tid & 1;
    float* gp = g + gbase + c * (HH * WWI) + qq * 4;
    const float* sp0 = sbuf + qq * 4 * XP + c;
#pragma unroll
    for (int i = 0; i < 8; ++i) {
        const float* sp = sp0 + i * 8 * XP;
        *(float4*)(gp + i * WWI) = make_float4(sp[0], sp[XP], sp[2 * XP], sp[3 * XP]);
    }
}

__global__ void __launch_bounds__(TB, 1) attn_k(const float* __restrict__ Q,
                                                const float* __restrict__ K,
                                                const float* __restrict__ V,
                                                float* __restrict__ O) {
    float* smem = (float*)smem_g;
    float* BQ = smem;
    float* BK = smem + BUF;
    float* BV = smem + 2 * BUF;

    const int tid = threadIdx.x;
    const int widx = blockIdx.x;
    const int b = widx >> 10;
    const int wh = (widx >> 5) & 31;
    const int ww = widx & 31;
    const int gbase = b * (CC * HH * WWI) + (wh * 8) * WWI + ww * 8;

    load_window(BQ, Q, gbase, tid);
    load_window(BK, K, gbase, tid);
    load_window(BV, V, gbase, tid);
    __syncthreads();

    const int L = tid & 31, w = tid >> 5;
    const int head = w >> 1;
    const int row = (w & 1) * 32 + L;

    u64 q[16];
    {
        const ulonglong2* qp = (const ulonglong2*)(BQ + row * XP + head * 32);
        const u64 sc2 = dup2(0.17677669529663687f);  // 32^-0.5
#pragma unroll
        for (int t = 0; t < 8; ++t) {
            ulonglong2 v = qp[t];
            q[2 * t]     = f2mul(v.x, sc2);
            q[2 * t + 1] = f2mul(v.y, sc2);
        }
    }
    __syncthreads();  // q in regs before BQ overwritten

    const float* kbase = BK + head * 32;
    const float* vbase = BV + head * 32;
    float l = 0.f;
    u64 o[16];
#pragma unroll
    for (int t = 0; t < 16; ++t) o[t] = 0ull;

    for (int j = 0; j < 64; ++j) {
        const ulonglong2* kp = (const ulonglong2*)(kbase + j * XP);
        u64 d0 = 0ull, d1 = 0ull, d2 = 0ull, d3 = 0ull;
#pragma unroll
        for (int t = 0; t < 4; ++t) {
            ulonglong2 ka = kp[2 * t], kb = kp[2 * t + 1];
            f2fma(d0, q[4 * t],     ka.x);
            f2fma(d1, q[4 * t + 1], ka.y);
            f2fma(d2, q[4 * t + 2], kb.x);
            f2fma(d3, q[4 * t + 3], kb.y);
        }
        const float e = __expf(f2sum(f2add(f2add(d0, d1), f2add(d2, d3))));
        l += e;
        const u64 ee = dup2(e);
        const ulonglong2* vp = (const ulonglong2*)(vbase + j * XP);
#pragma unroll
        for (int t = 0; t < 8; ++t) {
            ulonglong2 v2 = vp[t];
            f2fma(o[2 * t],     ee, v2.x);
            f2fma(o[2 * t + 1], ee, v2.y);
        }
    }
    const u64 inv2 = dup2(1.f / l);
    ulonglong2* op = (ulonglong2*)(BQ + row * XP + head * 32);
#pragma unroll
    for (int t = 0; t < 8; ++t) {
        ulonglong2 r;
        r.x = f2mul(o[2 * t], inv2);
        r.y = f2mul(o[2 * t + 1], inv2);
        op[t] = r;
    }
    __syncthreads();
    store_window(O, BQ, gbase, tid);
}

// ---------------------------------------------------------------------------
extern "C" void kernel_launch(void* const* d_in, const int* in_sizes, int n_in,
                              void* d_out, int out_size) {
    (void)in_sizes; (void)n_in; (void)out_size;

    // weight preprocessing
    preproc<<<64,  256>>>((const float*)d_in[2],  16384, OW_QO);
    preproc<<<64,  256>>>((const float*)d_in[4],  16384, OW_KO);
    preproc<<<64,  256>>>((const float*)d_in[6],  16384, OW_VO);
    preproc<<<64,  256>>>((const float*)d_in[8],  16384, OW_QS);
    preproc<<<64,  256>>>((const float*)d_in[10], 16384, OW_KS);
    preproc<<<64,  256>>>((const float*)d_in[12], 16384, OW_VS);
    preproc<<<64,  256>>>((const float*)d_in[14], 16384, OW_PO);
    preproc<<<64,  256>>>((const float*)d_in[16], 16384, OW_PS);
    preproc<<<128, 256>>>((const float*)d_in[18], 32768, OW_GO);
    preproc<<<128, 256>>>((const float*)d_in[20], 32768, OW_GS);
    preproc<<<128, 256>>>((const float*)d_in[22], 32768, OW_FW);

    float* scr = nullptr;
    cudaGetSymbolAddress((void**)&scr, g_scr);
    float* S0 = scr;
    float* S1 = scr + 1ull * NTOT;
    float* S2 = scr + 2ull * NTOT;
    float* S3 = scr + 3ull * NTOT;
    float* S4 = scr + 4ull * NTOT;
    float* S5 = scr + 5ull * NTOT;

    const float* F_opt = (const float*)d_in[0];
    const float* F_sar = (const float*)d_in[1];
    float* out = (float*)d_out;

    constexpr int SM128 = 2 * 128 * 136 * 2 + 2 * 128 * 136 * 2;  // 139264
    constexpr int SM256 = 2 * 128 * 264 * 2 + 2 * 128 * 136 * 2;  // 204800
    constexpr int SMATN = 3 * BUF * 4;                            // 101376
    cudaFuncSetAttribute(gemm_k<128, EPI_BIAS>,
                         cudaFuncAttributeMaxDynamicSharedMemorySize, SM128);
    cudaFuncSetAttribute(gemm_k<256, EPI_GATE>,
                         cudaFuncAttributeMaxDynamicSharedMemorySize, SM256);
    cudaFuncSetAttribute(gemm_k<256, EPI_FUSE>,
                         cudaFuncAttributeMaxDynamicSharedMemorySize, SM256);
    cudaFuncSetAttribute(attn_k,
                         cudaFuncAttributeMaxDynamicSharedMemorySize, SMATN);

    auto G = [&](const float* x0, const float* x1, int wOff, const float* bias,
                 float* dst, float* sgm, int epi,
                 const float* gma = nullptr, const float* bta = nullptr,
                 const float* mu = nullptr, const float* var = nullptr) {
        GP p{x0, x1, wOff, bias, dst, sgm, gma, bta, mu, var};
        if (epi == EPI_BIAS)      gemm_k<128, EPI_BIAS><<<256, TB, SM128>>>(p);
        else if (epi == EPI_GATE) gemm_k<256, EPI_GATE><<<256, TB, SM256>>>(p);
        else                      gemm_k<256, EPI_FUSE><<<256, TB, SM256>>>(p);
    };

    // QKV
    G(F_opt, nullptr, OW_QO, (const float*)d_in[3],  S0, nullptr, EPI_BIAS);
    G(F_opt, nullptr, OW_KO, (const float*)d_in[5],  S1, nullptr, EPI_BIAS);
    G(F_opt, nullptr, OW_VO, (const float*)d_in[7],  S2, nullptr, EPI_BIAS);
    G(F_sar, nullptr, OW_QS, (const float*)d_in[9],  S3, nullptr, EPI_BIAS);
    G(F_sar, nullptr, OW_KS, (const float*)d_in[11], S4, nullptr, EPI_BIAS);
    G(F_sar, nullptr, OW_VS, (const float*)d_in[13], S5, nullptr, EPI_BIAS);
    // window cross attention (in-place on Q scratch)
    attn_k<<<4096, TB, SMATN>>>(S0, S4, S5, S0);   // o2s
    attn_k<<<4096, TB, SMATN>>>(S3, S1, S2, S3);   // s2o
    // projections
    G(S0, nullptr, OW_PO, (const float*)d_in[15], S1, nullptr, EPI_BIAS); // F_o2s
    G(S3, nullptr, OW_PS, (const float*)d_in[17], S2, nullptr, EPI_BIAS); // F_s2o
    // gates (sigma out + residual)
    G(F_opt, S1, OW_GO, (const float*)d_in[19], S0, out + NTOT,     EPI_GATE);
    G(F_sar, S2, OW_GS, (const float*)d_in[21], S3, out + 2 * NTOT, EPI_GATE);
    // fuse + BN + SiLU
    G(S0, S3, OW_FW, (const float*)d_in[23], out, nullptr, EPI_FUSE,
      (const float*)d_in[24], (const float*)d_in[25],
      (const float*)d_in[26], (const float*)d_in[27]);
}